// round 13
// baseline (speedup 1.0000x reference)
#include <cuda_runtime.h>
#include <cuda_fp16.h>
#include <cstdint>

#define N_  512
#define C_  128
#define NN_ (N_*N_)

// ---------------------------------------------------------------------------
// global scratch (fp16 planes stored as uint32 = half2 of consecutive k pair)
// ---------------------------------------------------------------------------
__device__ uint32_t g_ath[(size_t)C_*(NN_/2)];  // a hi, c-major [c][(i*512+k)/2]
__device__ uint32_t g_atl[(size_t)C_*(NN_/2)];  // a lo
__device__ uint32_t g_bth[(size_t)C_*(NN_/2)];  // b hi
__device__ uint32_t g_wh [6*C_*64];             // weight hi planes [which][n][k/2]
__device__ uint32_t g_gt [(size_t)NN_*64];      // gate fp16 half2 [row][c/2]
__device__ uint32_t g_ot [(size_t)C_*(NN_/2)];  // einsum out fp16 half2, c-major

// ---------------------------------------------------------------------------
__device__ __forceinline__ float sigf(float x) { return 1.f / (1.f + __expf(-x)); }

__device__ __forceinline__ uint2 pack_split(float x0, float x1) {
    __half2 hh = __floats2half2_rn(x0, x1);
    float r0 = x0 - __half2float(__low2half(hh));
    float r1 = x1 - __half2float(__high2half(hh));
    __half2 ll = __floats2half2_rn(r0, r1);
    uint2 out;
    out.x = *reinterpret_cast<uint32_t*>(&hh);
    out.y = *reinterpret_cast<uint32_t*>(&ll);
    return out;
}
__device__ __forceinline__ uint32_t pack_h2(float x0, float x1) {
    __half2 hh = __floats2half2_rn(x0, x1);
    return *reinterpret_cast<uint32_t*>(&hh);
}

__device__ __forceinline__ void mma_f16(float* c, const uint32_t* a, const uint32_t* b) {
    asm volatile(
        "mma.sync.aligned.m16n8k16.row.col.f32.f16.f16.f32 "
        "{%0,%1,%2,%3},{%4,%5,%6,%7},{%8,%9},{%0,%1,%2,%3};\n"
        : "+f"(c[0]), "+f"(c[1]), "+f"(c[2]), "+f"(c[3])
        : "r"(a[0]), "r"(a[1]), "r"(a[2]), "r"(a[3]), "r"(b[0]), "r"(b[1]));
}

__device__ __forceinline__ uint32_t smem_u32(const void* p) {
    uint32_t a;
    asm("{ .reg .u64 t; cvta.to.shared.u64 t, %1; cvt.u32.u64 %0, t; }" : "=r"(a) : "l"(p));
    return a;
}
__device__ __forceinline__ void cp16s(uint32_t saddr, const void* g) {
    asm volatile("cp.async.cg.shared.global [%0], [%1], 16;\n" :: "r"(saddr), "l"(g));
}
__device__ __forceinline__ void cp_commit() { asm volatile("cp.async.commit_group;\n"); }
#define CP_WAIT(n) asm volatile("cp.async.wait_group %0;\n" :: "n"(n))

__device__ __forceinline__ void ldm_x4(uint32_t* r, uint32_t addr) {
    asm volatile("ldmatrix.sync.aligned.m8n8.x4.shared.b16 {%0,%1,%2,%3}, [%4];"
        : "=r"(r[0]), "=r"(r[1]), "=r"(r[2]), "=r"(r[3]) : "r"(addr));
}

#define MMA2T(acc, AH, AL, BH) do {      \
    mma_f16(acc, AH, BH);                \
    mma_f16(acc, AL, BH);                \
} while (0)

// ---------------------------------------------------------------------------
// 64xN x128 GEMM body (2-term fp16): X planes at xb (hi) / xb+XPLA (lo),
// W hi plane at wb (128 rows, stride 272B). 8 warps, warp tile 32x32 (2M x 4N).
// ---------------------------------------------------------------------------
#define XROW 272
#define XPL64 17408

template<int XPLA>
__device__ __forceinline__ void gemm64(uint32_t xb, uint32_t wb, float acc[2][4][4],
                                       int m0, int n0, int l16, uint32_t coff)
{
    #pragma unroll
    for (int kc = 0; kc < 8; kc++) {
        uint32_t kb = coff + kc*32;
        uint32_t Ah[2][4], Al[2][4];
        #pragma unroll
        for (int mt = 0; mt < 2; mt++) {
            uint32_t ar = (uint32_t)((m0 + mt*16 + l16) * XROW) + kb;
            ldm_x4(Ah[mt], xb + ar);
            ldm_x4(Al[mt], xb + XPLA + ar);
        }
        #pragma unroll
        for (int np = 0; np < 2; np++) {
            uint32_t br = (uint32_t)((n0 + np*16 + l16) * XROW) + kb;
            uint32_t Bh[4];
            ldm_x4(Bh, wb + br);
            #pragma unroll
            for (int h = 0; h < 2; h++) {
                uint32_t bh[2] = {Bh[h], Bh[2+h]};
                int nt = np*2 + h;
                #pragma unroll
                for (int mt = 0; mt < 2; mt++)
                    MMA2T(acc[mt][nt], Ah[mt], Al[mt], bh);
            }
        }
    }
}

// ---------------------------------------------------------------------------
// weight split -> hi planes.  order: ga=0, pa=1, gb=2, pb=3, g=4, o=5
// ---------------------------------------------------------------------------
__global__ __launch_bounds__(256) void split_w_lm(
    const float* __restrict__ w0, const float* __restrict__ w1,
    const float* __restrict__ w2, const float* __restrict__ w3,
    const float* __restrict__ w4, const float* __restrict__ w5,
    uint32_t* __restrict__ wh)
{
    int which = blockIdx.y;
    const float* w = which==0?w0 : which==1?w1 : which==2?w2 :
                     which==3?w3 : which==4?w4 : w5;
    int e = blockIdx.x*256 + threadIdx.x;
    int n = e >> 6, kk = e & 63;
    wh[which*C_*64 + e] = pack_h2(w[n*C_ + 2*kk], w[n*C_ + 2*kk + 1]);
}

// ---------------------------------------------------------------------------
// proj_fused: 64-row tile, 256 thr, 2 CTAs/SM.  (unchanged from R12)
// ---------------------------------------------------------------------------
#define PJ_B0   34816
#define PJ_B1   69632
#define PJ_WS   104448
#define PJ_SMEM 105472

__global__ __launch_bounds__(256, 2) void proj_fused(
    const float* __restrict__ z, const float* __restrict__ mask,
    const float* __restrict__ lnw, const float* __restrict__ lnb,
    const uint32_t* __restrict__ WH,
    uint32_t* __restrict__ aH, uint32_t* __restrict__ aL,
    uint32_t* __restrict__ bH,
    uint32_t* __restrict__ gate)
{
    extern __shared__ char sm[];
    uint32_t sb = smem_u32(sm);
    int t = threadIdx.x, warp = t>>5, lane = t&31, g = lane>>2, tg = lane&3;
    int l16 = lane & 15;
    uint32_t coff = (uint32_t)((lane >> 4) * 16);
    int m0 = (warp & 1) * 32, n0 = (warp >> 1) * 32;
    size_t row0 = (size_t)blockIdx.x * 64;

    auto loadW = [&](int which, uint32_t dst) {
        const uint32_t* srcH = WH + which*8192;
        #pragma unroll
        for (int i = 0; i < 8; i++) {
            int e = i*256 + t;
            int r = e >> 4, ch = e & 15;
            cp16s(dst + (uint32_t)(r*XROW + ch*16), srcH + (size_t)r*64 + ch*4);
        }
        cp_commit();
    };

    {
        const char* zp = (const char*)(z + row0*C_);
        #pragma unroll
        for (int i = 0; i < 8; i++) {
            int e = i*256 + t, r = e >> 5, c4 = e & 31;
            cp16s(sb + (uint32_t)(r*528 + c4*16), zp + (size_t)r*512 + c4*16);
        }
        cp_commit();
    }
    loadW(0, sb + PJ_B0);   // ga
    loadW(1, sb + PJ_B1);   // pa

    if (t < 128) {
        ((float*)(sm + PJ_WS))[t]       = lnw[t];
        ((float*)(sm + PJ_WS))[128 + t] = lnb[t];
    }

    CP_WAIT(2);
    __syncthreads();

    {
        float* s  = (float*)sm;
        float* wv = (float*)(sm + PJ_WS);
        int r = t >> 2, q = t & 3;
        float y[32];
        float s1 = 0.f, s2 = 0.f;
        #pragma unroll
        for (int i = 0; i < 32; i++) {
            float v = s[r*132 + q*32 + i];
            y[i] = v; s1 += v; s2 += v*v;
        }
        s1 += __shfl_xor_sync(~0u, s1, 1); s2 += __shfl_xor_sync(~0u, s2, 1);
        s1 += __shfl_xor_sync(~0u, s1, 2); s2 += __shfl_xor_sync(~0u, s2, 2);
        float mu  = s1 * (1.f/128.f);
        float var = s2 * (1.f/128.f) - mu*mu;
        float inv = rsqrtf(var + 1e-5f);
        __syncthreads();
        uint32_t* xh = (uint32_t*)(sm + r*XROW);
        uint32_t* xl = (uint32_t*)(sm + XPL64 + r*XROW);
        #pragma unroll
        for (int j = 0; j < 16; j++) {
            int c0 = q*32 + 2*j;
            float y0 = (y[2*j]   - mu) * inv * wv[c0]   + wv[128 + c0];
            float y1 = (y[2*j+1] - mu) * inv * wv[c0+1] + wv[128 + c0 + 1];
            uint2 p = pack_split(y0, y1);
            xh[q*16 + j] = p.x;
            xl[q*16 + j] = p.y;
        }
    }
    __syncthreads();

    float acc1[2][4][4], acc2[2][4][4];
    auto zacc = [&]() {
        #pragma unroll
        for (int mt = 0; mt < 2; mt++)
            #pragma unroll
            for (int nt = 0; nt < 4; nt++)
                #pragma unroll
                for (int q = 0; q < 4; q++) { acc1[mt][nt][q] = 0.f; acc2[mt][nt][q] = 0.f; }
    };

    auto epi_ab = [&](uint32_t* Yh, uint32_t* Yl) {
        __syncthreads();
        float* so = (float*)(sm + PJ_B0);
        #pragma unroll
        for (int mt = 0; mt < 2; mt++) {
            int rl = m0 + mt*16 + g, rh = rl + 8;
            float ml = mask[row0 + rl], mh = mask[row0 + rh];
            #pragma unroll
            for (int nt = 0; nt < 4; nt++) {
                int cl = n0 + nt*8 + 2*tg;
                so[rl*132 + cl]     = ml * sigf(acc1[mt][nt][0]) * acc2[mt][nt][0];
                so[rl*132 + cl + 1] = ml * sigf(acc1[mt][nt][1]) * acc2[mt][nt][1];
                so[rh*132 + cl]     = mh * sigf(acc1[mt][nt][2]) * acc2[mt][nt][2];
                so[rh*132 + cl + 1] = mh * sigf(acc1[mt][nt][3]) * acc2[mt][nt][3];
            }
        }
        __syncthreads();
        int c = t >> 1, p0 = (t & 1) * 16;
        size_t ub = (size_t)c * (NN_/2) + row0/2;
        #pragma unroll
        for (int p = 0; p < 16; p++) {
            int pr = p0 + p;
            uint2 pv = pack_split(so[(2*pr)*132 + c], so[(2*pr+1)*132 + c]);
            Yh[ub + pr] = pv.x;
            if (Yl) Yl[ub + pr] = pv.y;
        }
        __syncthreads();
    };

    // ---- ga,pa -> a ----
    zacc();
    CP_WAIT(1); __syncthreads();
    gemm64<XPL64>(sb, sb + PJ_B0, acc1, m0, n0, l16, coff);      // ga
    CP_WAIT(0); __syncthreads();
    gemm64<XPL64>(sb, sb + PJ_B1, acc2, m0, n0, l16, coff);      // pa
    __syncthreads();
    loadW(2, sb + PJ_B1);          // gb
    epi_ab(aH, aL);
    loadW(3, sb + PJ_B0);          // pb
    // ---- gb,pb -> b ----
    zacc();
    CP_WAIT(1); __syncthreads();
    gemm64<XPL64>(sb, sb + PJ_B1, acc1, m0, n0, l16, coff);      // gb
    CP_WAIT(0); __syncthreads();
    gemm64<XPL64>(sb, sb + PJ_B0, acc2, m0, n0, l16, coff);      // pb
    __syncthreads();
    loadW(4, sb + PJ_B1);          // wg
    epi_ab(bH, nullptr);
    // ---- wg -> gate (fp16 packed) ----
    zacc();
    CP_WAIT(0); __syncthreads();
    gemm64<XPL64>(sb, sb + PJ_B1, acc1, m0, n0, l16, coff);      // wg

    #pragma unroll
    for (int mt = 0; mt < 2; mt++) {
        size_t rl = row0 + m0 + mt*16 + g;
        size_t rh = rl + 8;
        #pragma unroll
        for (int nt = 0; nt < 4; nt++) {
            int cl = n0 + nt*8 + 2*tg;
            gate[rl*64 + cl/2] = pack_h2(sigf(acc1[mt][nt][0]), sigf(acc1[mt][nt][1]));
            gate[rh*64 + cl/2] = pack_h2(sigf(acc1[mt][nt][2]), sigf(acc1[mt][nt][3]));
        }
    }
}

// ---------------------------------------------------------------------------
// tri: per channel cz, 128x128 tile, K=512 in 16 stages.
// NEW: 512 threads, 16 warps (4M x 4N, warp tile 32x32), 2 CTAs/SM
// -> 32 warps/SM. acc = 32 regs; hi/lo A fragments phased to fit 64-reg cap.
// ---------------------------------------------------------------------------
#define TSROW 80
#define TPLANE (128*TSROW)
#define TR_STAGE (3*TPLANE)
#define TR_SMEM  (2*TR_STAGE)

__global__ __launch_bounds__(512, 2) void tri_lm(
    const uint32_t* __restrict__ AhG, const uint32_t* __restrict__ AlG,
    const uint32_t* __restrict__ BhG,
    uint32_t* __restrict__ Ot)
{
    extern __shared__ char smraw[];
    uint32_t sb = smem_u32(smraw);
    int t = threadIdx.x, warp = t>>5, lane = t&31, g = lane>>2, tg = lane&3;
    int j0 = blockIdx.x * 128, i0 = blockIdx.y * 128, cz = blockIdx.z;
    int m0 = (warp & 3) * 32, n0 = (warp >> 2) * 32;

    size_t cb = (size_t)cz * (NN_/2);
    const char* p0 = (const char*)(AhG + cb + (size_t)i0*256);
    const char* p1 = (const char*)(AlG + cb + (size_t)i0*256);
    const char* p2 = (const char*)(BhG + cb + (size_t)j0*256);

    // loader: 3 planes x 128 rows x 4 chunks(16B) = 1536 cp16 / 512 thr = 3 each
    auto load_stage = [&](int st, int slot) {
        uint32_t base = sb + slot*TR_STAGE;
        #pragma unroll
        for (int i = 0; i < 3; i++) {
            int e = i*512 + t;                 // 0..1535
            int pl = e >> 9;
            int w_ = e & 511;
            int r = w_ >> 2, ch = (w_ & 3) * 16;
            const char* src = pl == 0 ? p0 : (pl == 1 ? p1 : p2);
            cp16s(base + (uint32_t)(pl*TPLANE + r*TSROW + ch),
                  src + (size_t)r*1024 + st*64 + ch);
        }
        cp_commit();
    };

    float acc[2][4][4];
    #pragma unroll
    for (int mt=0; mt<2; mt++)
        #pragma unroll
        for (int nt=0; nt<4; nt++)
            #pragma unroll
            for (int q=0; q<4; q++) acc[mt][nt][q]=0.f;

    int l16 = lane & 15;
    uint32_t coff = (uint32_t)((lane >> 4) * 16);

    load_stage(0, 0);
    load_stage(1, 1);

    #pragma unroll 1
    for (int st = 0; st < 16; st++) {
        if (st < 15) CP_WAIT(1); else CP_WAIT(0);
        __syncthreads();
        uint32_t base = sb + (st & 1)*TR_STAGE;
        #pragma unroll
        for (int kc = 0; kc < 2; kc++) {
            uint32_t kb = coff + kc*32;
            // B fragments for warp's 32 N rows (both halves)
            uint32_t B2[2][4];
            ldm_x4(B2[0], base + 2*TPLANE + (uint32_t)((n0 + l16) * TSROW) + kb);
            ldm_x4(B2[1], base + 2*TPLANE + (uint32_t)((n0 + 16 + l16) * TSROW) + kb);
            // hi pass
            uint32_t Aq[2][4];
            #pragma unroll
            for (int mt=0; mt<2; mt++)
                ldm_x4(Aq[mt], base + (uint32_t)((m0 + mt*16 + l16) * TSROW) + kb);
            #pragma unroll
            for (int np=0; np<2; np++)
                #pragma unroll
                for (int h=0; h<2; h++) {
                    uint32_t bh[2] = {B2[np][h], B2[np][2+h]};
                    #pragma unroll
                    for (int mt=0; mt<2; mt++)
                        mma_f16(acc[mt][np*2+h], Aq[mt], bh);
                }
            // lo pass (reuse Aq registers)
            #pragma unroll
            for (int mt=0; mt<2; mt++)
                ldm_x4(Aq[mt], base + TPLANE + (uint32_t)((m0 + mt*16 + l16) * TSROW) + kb);
            #pragma unroll
            for (int np=0; np<2; np++)
                #pragma unroll
                for (int h=0; h<2; h++) {
                    uint32_t bh[2] = {B2[np][h], B2[np][2+h]};
                    #pragma unroll
                    for (int mt=0; mt<2; mt++)
                        mma_f16(acc[mt][np*2+h], Aq[mt], bh);
                }
        }
        __syncthreads();
        if (st + 2 < 16) load_stage(st + 2, st & 1);
    }

    uint32_t* O = Ot + (size_t)cz*(NN_/2);
    #pragma unroll
    for (int mt=0; mt<2; mt++) {
        int r = i0 + m0 + mt*16 + g;
        #pragma unroll
        for (int nt=0; nt<4; nt++) {
            int cl = j0 + n0 + nt*8 + 2*tg;
            O[(size_t)r*(N_/2) + cl/2]     = pack_h2(acc[mt][nt][0], acc[mt][nt][1]);
            O[(size_t)(r+8)*(N_/2) + cl/2] = pack_h2(acc[mt][nt][2], acc[mt][nt][3]);
        }
    }
}

// ---------------------------------------------------------------------------
// out_fused: 64-ij tile, 256 thr, 3 CTAs/SM.  (unchanged from R12)
// ---------------------------------------------------------------------------
#define OF_WO   34816
#define OF_WS   69632
#define OF_SMEM 70656

__global__ __launch_bounds__(256, 3) void out_fused(
    const uint32_t* __restrict__ ot, const uint32_t* __restrict__ gate,
    const float* __restrict__ lnw, const float* __restrict__ lnb,
    const uint32_t* __restrict__ WoH,
    float* __restrict__ out)
{
    extern __shared__ char sm[];
    uint32_t sb = smem_u32(sm);
    int t = threadIdx.x, warp = t>>5, lane = t&31, g = lane>>2, tg = lane&3;
    int l16 = lane & 15;
    uint32_t coff = (uint32_t)((lane >> 4) * 16);
    int m0 = (warp & 1) * 32, n0 = (warp >> 1) * 32;
    size_t ij0 = (size_t)blockIdx.x * 64;

    #pragma unroll
    for (int i = 0; i < 4; i++) {
        int e = i*256 + t, c = e >> 3, ch = e & 7;
        cp16s(sb + (uint32_t)(c*XROW + ch*16),
              (const char*)(ot + (size_t)c*(NN_/2) + ij0/2) + ch*16);
    }
    cp_commit();
    #pragma unroll
    for (int i = 0; i < 8; i++) {
        int e = i*256 + t;
        int r = e >> 4, ch = e & 15;
        cp16s(sb + OF_WO + (uint32_t)(r*XROW + ch*16), WoH + (size_t)r*64 + ch*4);
    }
    cp_commit();

    if (t < 128) {
        ((float*)(sm + OF_WS))[t]       = lnw[t];
        ((float*)(sm + OF_WS))[128 + t] = lnb[t];
    }

    CP_WAIT(1); __syncthreads();

    {
        float* wv = (float*)(sm + OF_WS);
        int ij = t >> 2, q = t & 3;
        float y[32];
        float s1 = 0.f, s2 = 0.f;
        #pragma unroll
        for (int i = 0; i < 32; i++) {
            int c = q*32 + i;
            __half h = *(const __half*)(sm + c*XROW + ij*2);
            float v = __half2float(h);
            y[i] = v; s1 += v; s2 += v*v;
        }
        s1 += __shfl_xor_sync(~0u, s1, 1); s2 += __shfl_xor_sync(~0u, s2, 1);
        s1 += __shfl_xor_sync(~0u, s1, 2); s2 += __shfl_xor_sync(~0u, s2, 2);
        float mu  = s1 * (1.f/128.f);
        float var = s2 * (1.f/128.f) - mu*mu;
        float inv = rsqrtf(var + 1e-5f);
        __syncthreads();
        uint32_t* oh = (uint32_t*)(sm + ij*XROW);
        uint32_t* ol = (uint32_t*)(sm + XPL64 + ij*XROW);
        #pragma unroll
        for (int j = 0; j < 16; j++) {
            int c0 = q*32 + 2*j;
            float y0 = (y[2*j]   - mu) * inv * wv[c0]   + wv[128 + c0];
            float y1 = (y[2*j+1] - mu) * inv * wv[c0+1] + wv[128 + c0 + 1];
            uint2 p = pack_split(y0, y1);
            oh[q*16 + j] = p.x;
            ol[q*16 + j] = p.y;
        }
    }
    CP_WAIT(0); __syncthreads();

    float acc[2][4][4];
    #pragma unroll
    for (int mt=0; mt<2; mt++)
        #pragma unroll
        for (int nt=0; nt<4; nt++)
            #pragma unroll
            for (int q=0; q<4; q++) acc[mt][nt][q]=0.f;

    gemm64<XPL64>(sb, sb + OF_WO, acc, m0, n0, l16, coff);

    #pragma unroll
    for (int mt=0; mt<2; mt++) {
        size_t rl = ij0 + m0 + mt*16 + g;
        size_t rh = rl + 8;
        #pragma unroll
        for (int nt=0; nt<4; nt++) {
            int cl = n0 + nt*8 + 2*tg;
            __half2 glh = *(const __half2*)(gate + rl*64 + cl/2);
            __half2 ghh = *(const __half2*)(gate + rh*64 + cl/2);
            float2 gl = __half22float2(glh);
            float2 gh = __half22float2(ghh);
            *(float2*)(out + rl*C_ + cl) =
                make_float2(gl.x * acc[mt][nt][0], gl.y * acc[mt][nt][1]);
            *(float2*)(out + rh*C_ + cl) =
                make_float2(gh.x * acc[mt][nt][2], gh.y * acc[mt][nt][3]);
        }
    }
}

// ---------------------------------------------------------------------------
extern "C" void kernel_launch(void* const* d_in, const int* in_sizes, int n_in,
                              void* d_out, int out_size)
{
    const float* z      = (const float*)d_in[0];
    const float* mask   = (const float*)d_in[1];
    const float* ln_i_w = (const float*)d_in[2];
    const float* ln_i_b = (const float*)d_in[3];
    const float* ln_o_w = (const float*)d_in[4];
    const float* ln_o_b = (const float*)d_in[5];
    const float* w_pa   = (const float*)d_in[6];
    const float* w_pb   = (const float*)d_in[7];
    const float* w_ga   = (const float*)d_in[8];
    const float* w_gb   = (const float*)d_in[9];
    const float* w_g    = (const float*)d_in[10];
    const float* w_o    = (const float*)d_in[11];
    float* out = (float*)d_out;

    uint32_t *ath, *atl, *bth, *wh, *gt, *ot;
    cudaGetSymbolAddress((void**)&ath, g_ath);
    cudaGetSymbolAddress((void**)&atl, g_atl);
    cudaGetSymbolAddress((void**)&bth, g_bth);
    cudaGetSymbolAddress((void**)&wh,  g_wh);
    cudaGetSymbolAddress((void**)&gt,  g_gt);
    cudaGetSymbolAddress((void**)&ot,  g_ot);

    cudaFuncSetAttribute(proj_fused, cudaFuncAttributeMaxDynamicSharedMemorySize, PJ_SMEM);
    cudaFuncSetAttribute(out_fused,  cudaFuncAttributeMaxDynamicSharedMemorySize, OF_SMEM);
    cudaFuncSetAttribute(tri_lm,     cudaFuncAttributeMaxDynamicSharedMemorySize, TR_SMEM);

    // weight plane order: ga=0, pa=1, gb=2, pb=3, g=4, o=5
    split_w_lm<<<dim3(32, 6), 256>>>(w_ga, w_pa, w_gb, w_pb, w_g, w_o, wh);
    // LN(z) + 5 projections fused (64-row tiles, 2 CTAs/SM)
    proj_fused<<<NN_/64, 256, PJ_SMEM>>>(z, mask, ln_i_w, ln_i_b, wh,
                                         ath, atl, bth, gt);
    // triangle einsum -> ot fp16 c-major (512 thr, 2 CTAs/SM = 32 warps/SM)
    tri_lm<<<dim3(N_/128, N_/128, C_), 512, TR_SMEM>>>(ath, atl, bth, ot);
    // transpose+LN+GEMM+gate fused (64-ij tiles, 3 CTAs/SM)
    out_fused<<<NN_/64, 256, OF_SMEM>>>(ot, gt, ln_o_w, ln_o_b,
                                        wh + 5*C_*64, out);
}

// round 14
// speedup vs baseline: 1.1959x; 1.1959x over previous
#include <cuda_runtime.h>
#include <cuda_fp16.h>
#include <cstdint>

#define N_  512
#define C_  128
#define NN_ (N_*N_)

// ---------------------------------------------------------------------------
// global scratch (fp16 planes stored as uint32 = half2 of consecutive k pair)
// ---------------------------------------------------------------------------
__device__ uint32_t g_ath[(size_t)C_*(NN_/2)];  // a hi, c-major [c][(i*512+k)/2]
__device__ uint32_t g_bth[(size_t)C_*(NN_/2)];  // b hi
__device__ uint32_t g_wh [6*C_*64];             // weight hi planes [which][n][k/2]
__device__ uint32_t g_gt [(size_t)NN_*64];      // gate fp16 half2 [row][c/2]
__device__ uint32_t g_ot [(size_t)C_*(NN_/2)];  // einsum out fp16 half2, c-major

// ---------------------------------------------------------------------------
__device__ __forceinline__ float sigf(float x) { return 1.f / (1.f + __expf(-x)); }

__device__ __forceinline__ uint2 pack_split(float x0, float x1) {
    __half2 hh = __floats2half2_rn(x0, x1);
    float r0 = x0 - __half2float(__low2half(hh));
    float r1 = x1 - __half2float(__high2half(hh));
    __half2 ll = __floats2half2_rn(r0, r1);
    uint2 out;
    out.x = *reinterpret_cast<uint32_t*>(&hh);
    out.y = *reinterpret_cast<uint32_t*>(&ll);
    return out;
}
__device__ __forceinline__ uint32_t pack_h2(float x0, float x1) {
    __half2 hh = __floats2half2_rn(x0, x1);
    return *reinterpret_cast<uint32_t*>(&hh);
}

__device__ __forceinline__ void mma_f16(float* c, const uint32_t* a, const uint32_t* b) {
    asm volatile(
        "mma.sync.aligned.m16n8k16.row.col.f32.f16.f16.f32 "
        "{%0,%1,%2,%3},{%4,%5,%6,%7},{%8,%9},{%0,%1,%2,%3};\n"
        : "+f"(c[0]), "+f"(c[1]), "+f"(c[2]), "+f"(c[3])
        : "r"(a[0]), "r"(a[1]), "r"(a[2]), "r"(a[3]), "r"(b[0]), "r"(b[1]));
}

__device__ __forceinline__ uint32_t smem_u32(const void* p) {
    uint32_t a;
    asm("{ .reg .u64 t; cvta.to.shared.u64 t, %1; cvt.u32.u64 %0, t; }" : "=r"(a) : "l"(p));
    return a;
}
__device__ __forceinline__ void cp16s(uint32_t saddr, const void* g) {
    asm volatile("cp.async.cg.shared.global [%0], [%1], 16;\n" :: "r"(saddr), "l"(g));
}
__device__ __forceinline__ void cp_commit() { asm volatile("cp.async.commit_group;\n"); }
#define CP_WAIT(n) asm volatile("cp.async.wait_group %0;\n" :: "n"(n))

__device__ __forceinline__ void ldm_x4(uint32_t* r, uint32_t addr) {
    asm volatile("ldmatrix.sync.aligned.m8n8.x4.shared.b16 {%0,%1,%2,%3}, [%4];"
        : "=r"(r[0]), "=r"(r[1]), "=r"(r[2]), "=r"(r[3]) : "r"(addr));
}

#define MMA2T(acc, AH, AL, BH) do {      \
    mma_f16(acc, AH, BH);                \
    mma_f16(acc, AL, BH);                \
} while (0)

// ---------------------------------------------------------------------------
// 64xN x128 GEMM body (2-term fp16): X planes at xb (hi) / xb+XPLA (lo),
// W hi plane at wb (128 rows, stride 272B). 8 warps, warp tile 32x32 (2M x 4N).
// ---------------------------------------------------------------------------
#define XROW 272
#define XPL64 17408

template<int XPLA>
__device__ __forceinline__ void gemm64(uint32_t xb, uint32_t wb, float acc[2][4][4],
                                       int m0, int n0, int l16, uint32_t coff)
{
    #pragma unroll
    for (int kc = 0; kc < 8; kc++) {
        uint32_t kb = coff + kc*32;
        uint32_t Ah[2][4], Al[2][4];
        #pragma unroll
        for (int mt = 0; mt < 2; mt++) {
            uint32_t ar = (uint32_t)((m0 + mt*16 + l16) * XROW) + kb;
            ldm_x4(Ah[mt], xb + ar);
            ldm_x4(Al[mt], xb + XPLA + ar);
        }
        #pragma unroll
        for (int np = 0; np < 2; np++) {
            uint32_t br = (uint32_t)((n0 + np*16 + l16) * XROW) + kb;
            uint32_t Bh[4];
            ldm_x4(Bh, wb + br);
            #pragma unroll
            for (int h = 0; h < 2; h++) {
                uint32_t bh[2] = {Bh[h], Bh[2+h]};
                int nt = np*2 + h;
                #pragma unroll
                for (int mt = 0; mt < 2; mt++)
                    MMA2T(acc[mt][nt], Ah[mt], Al[mt], bh);
            }
        }
    }
}

// ---------------------------------------------------------------------------
// weight split -> hi planes.  order: ga=0, pa=1, gb=2, pb=3, g=4, o=5
// ---------------------------------------------------------------------------
__global__ __launch_bounds__(256) void split_w_lm(
    const float* __restrict__ w0, const float* __restrict__ w1,
    const float* __restrict__ w2, const float* __restrict__ w3,
    const float* __restrict__ w4, const float* __restrict__ w5,
    uint32_t* __restrict__ wh)
{
    int which = blockIdx.y;
    const float* w = which==0?w0 : which==1?w1 : which==2?w2 :
                     which==3?w3 : which==4?w4 : w5;
    int e = blockIdx.x*256 + threadIdx.x;
    int n = e >> 6, kk = e & 63;
    wh[which*C_*64 + e] = pack_h2(w[n*C_ + 2*kk], w[n*C_ + 2*kk + 1]);
}

// ---------------------------------------------------------------------------
// proj_fused: 64-row tile, 256 thr, 2 CTAs/SM.  (a/b now hi-plane only)
// ---------------------------------------------------------------------------
#define PJ_B0   34816
#define PJ_B1   69632
#define PJ_WS   104448
#define PJ_SMEM 105472

__global__ __launch_bounds__(256, 2) void proj_fused(
    const float* __restrict__ z, const float* __restrict__ mask,
    const float* __restrict__ lnw, const float* __restrict__ lnb,
    const uint32_t* __restrict__ WH,
    uint32_t* __restrict__ aH, uint32_t* __restrict__ bH,
    uint32_t* __restrict__ gate)
{
    extern __shared__ char sm[];
    uint32_t sb = smem_u32(sm);
    int t = threadIdx.x, warp = t>>5, lane = t&31, g = lane>>2, tg = lane&3;
    int l16 = lane & 15;
    uint32_t coff = (uint32_t)((lane >> 4) * 16);
    int m0 = (warp & 1) * 32, n0 = (warp >> 1) * 32;
    size_t row0 = (size_t)blockIdx.x * 64;

    auto loadW = [&](int which, uint32_t dst) {
        const uint32_t* srcH = WH + which*8192;
        #pragma unroll
        for (int i = 0; i < 8; i++) {
            int e = i*256 + t;
            int r = e >> 4, ch = e & 15;
            cp16s(dst + (uint32_t)(r*XROW + ch*16), srcH + (size_t)r*64 + ch*4);
        }
        cp_commit();
    };

    {
        const char* zp = (const char*)(z + row0*C_);
        #pragma unroll
        for (int i = 0; i < 8; i++) {
            int e = i*256 + t, r = e >> 5, c4 = e & 31;
            cp16s(sb + (uint32_t)(r*528 + c4*16), zp + (size_t)r*512 + c4*16);
        }
        cp_commit();
    }
    loadW(0, sb + PJ_B0);   // ga
    loadW(1, sb + PJ_B1);   // pa

    if (t < 128) {
        ((float*)(sm + PJ_WS))[t]       = lnw[t];
        ((float*)(sm + PJ_WS))[128 + t] = lnb[t];
    }

    CP_WAIT(2);
    __syncthreads();

    {
        float* s  = (float*)sm;
        float* wv = (float*)(sm + PJ_WS);
        int r = t >> 2, q = t & 3;
        float y[32];
        float s1 = 0.f, s2 = 0.f;
        #pragma unroll
        for (int i = 0; i < 32; i++) {
            float v = s[r*132 + q*32 + i];
            y[i] = v; s1 += v; s2 += v*v;
        }
        s1 += __shfl_xor_sync(~0u, s1, 1); s2 += __shfl_xor_sync(~0u, s2, 1);
        s1 += __shfl_xor_sync(~0u, s1, 2); s2 += __shfl_xor_sync(~0u, s2, 2);
        float mu  = s1 * (1.f/128.f);
        float var = s2 * (1.f/128.f) - mu*mu;
        float inv = rsqrtf(var + 1e-5f);
        __syncthreads();
        uint32_t* xh = (uint32_t*)(sm + r*XROW);
        uint32_t* xl = (uint32_t*)(sm + XPL64 + r*XROW);
        #pragma unroll
        for (int j = 0; j < 16; j++) {
            int c0 = q*32 + 2*j;
            float y0 = (y[2*j]   - mu) * inv * wv[c0]   + wv[128 + c0];
            float y1 = (y[2*j+1] - mu) * inv * wv[c0+1] + wv[128 + c0 + 1];
            uint2 p = pack_split(y0, y1);
            xh[q*16 + j] = p.x;
            xl[q*16 + j] = p.y;
        }
    }
    __syncthreads();

    float acc1[2][4][4], acc2[2][4][4];
    auto zacc = [&]() {
        #pragma unroll
        for (int mt = 0; mt < 2; mt++)
            #pragma unroll
            for (int nt = 0; nt < 4; nt++)
                #pragma unroll
                for (int q = 0; q < 4; q++) { acc1[mt][nt][q] = 0.f; acc2[mt][nt][q] = 0.f; }
    };

    // epilogue: y = mask*sig(acc1)*acc2 -> c-major packed hi plane
    auto epi_ab = [&](uint32_t* Yh) {
        __syncthreads();
        float* so = (float*)(sm + PJ_B0);
        #pragma unroll
        for (int mt = 0; mt < 2; mt++) {
            int rl = m0 + mt*16 + g, rh = rl + 8;
            float ml = mask[row0 + rl], mh = mask[row0 + rh];
            #pragma unroll
            for (int nt = 0; nt < 4; nt++) {
                int cl = n0 + nt*8 + 2*tg;
                so[rl*132 + cl]     = ml * sigf(acc1[mt][nt][0]) * acc2[mt][nt][0];
                so[rl*132 + cl + 1] = ml * sigf(acc1[mt][nt][1]) * acc2[mt][nt][1];
                so[rh*132 + cl]     = mh * sigf(acc1[mt][nt][2]) * acc2[mt][nt][2];
                so[rh*132 + cl + 1] = mh * sigf(acc1[mt][nt][3]) * acc2[mt][nt][3];
            }
        }
        __syncthreads();
        int c = t >> 1, p0 = (t & 1) * 16;
        size_t ub = (size_t)c * (NN_/2) + row0/2;
        #pragma unroll
        for (int p = 0; p < 16; p++) {
            int pr = p0 + p;
            Yh[ub + pr] = pack_h2(so[(2*pr)*132 + c], so[(2*pr+1)*132 + c]);
        }
        __syncthreads();
    };

    // ---- ga,pa -> a ----
    zacc();
    CP_WAIT(1); __syncthreads();
    gemm64<XPL64>(sb, sb + PJ_B0, acc1, m0, n0, l16, coff);      // ga
    CP_WAIT(0); __syncthreads();
    gemm64<XPL64>(sb, sb + PJ_B1, acc2, m0, n0, l16, coff);      // pa
    __syncthreads();
    loadW(2, sb + PJ_B1);          // gb
    epi_ab(aH);
    loadW(3, sb + PJ_B0);          // pb
    // ---- gb,pb -> b ----
    zacc();
    CP_WAIT(1); __syncthreads();
    gemm64<XPL64>(sb, sb + PJ_B1, acc1, m0, n0, l16, coff);      // gb
    CP_WAIT(0); __syncthreads();
    gemm64<XPL64>(sb, sb + PJ_B0, acc2, m0, n0, l16, coff);      // pb
    __syncthreads();
    loadW(4, sb + PJ_B1);          // wg
    epi_ab(bH);
    // ---- wg -> gate (fp16 packed) ----
    zacc();
    CP_WAIT(0); __syncthreads();
    gemm64<XPL64>(sb, sb + PJ_B1, acc1, m0, n0, l16, coff);      // wg

    #pragma unroll
    for (int mt = 0; mt < 2; mt++) {
        size_t rl = row0 + m0 + mt*16 + g;
        size_t rh = rl + 8;
        #pragma unroll
        for (int nt = 0; nt < 4; nt++) {
            int cl = n0 + nt*8 + 2*tg;
            gate[rl*64 + cl/2] = pack_h2(sigf(acc1[mt][nt][0]), sigf(acc1[mt][nt][1]));
            gate[rh*64 + cl/2] = pack_h2(sigf(acc1[mt][nt][2]), sigf(acc1[mt][nt][3]));
        }
    }
}

// ---------------------------------------------------------------------------
// tri: per channel cz, 128x128 tile, K=512 in 16 stages of k32.
// 1-TERM fp16 (A hi x B hi only). 256 thr, 8 warps (4M x 2N), 2 CTAs/SM.
// 2 planes per stage, 3-slot cp.async ring.
// ---------------------------------------------------------------------------
#define TSROW 80
#define TPLANE (128*TSROW)
#define TR_STAGE (2*TPLANE)          // 20480
#define TR_SMEM  (3*TR_STAGE)        // 61440

__global__ __launch_bounds__(256, 2) void tri_lm(
    const uint32_t* __restrict__ AhG, const uint32_t* __restrict__ BhG,
    uint32_t* __restrict__ Ot)
{
    extern __shared__ char smraw[];
    uint32_t sb = smem_u32(smraw);
    int t = threadIdx.x, warp = t>>5, lane = t&31, g = lane>>2, tg = lane&3;
    int j0 = blockIdx.x * 128, i0 = blockIdx.y * 128, cz = blockIdx.z;
    int m0 = (warp & 3) * 32, n0 = (warp >> 2) * 64;

    size_t cb = (size_t)cz * (NN_/2);
    const char* p0 = (const char*)(AhG + cb + (size_t)i0*256);
    const char* p2 = (const char*)(BhG + cb + (size_t)j0*256);

    // loader: 2 planes x 128 rows x 4 chunks = 1024 cp16 / 256 thr = 4 each
    auto load_stage = [&](int st, int slot) {
        uint32_t base = sb + slot*TR_STAGE;
        #pragma unroll
        for (int i = 0; i < 4; i++) {
            int e = i*256 + t;                 // 0..1023
            int pl = e >> 9;
            int w_ = e & 511;
            int r = w_ >> 2, ch = (w_ & 3) * 16;
            const char* src = pl ? p2 : p0;
            cp16s(base + (uint32_t)(pl*TPLANE + r*TSROW + ch),
                  src + (size_t)r*1024 + st*64 + ch);
        }
        cp_commit();
    };

    float acc[2][8][4];
    #pragma unroll
    for (int mt=0; mt<2; mt++)
        #pragma unroll
        for (int nt=0; nt<8; nt++)
            #pragma unroll
            for (int q=0; q<4; q++) acc[mt][nt][q]=0.f;

    int l16 = lane & 15;
    uint32_t coff = (uint32_t)((lane >> 4) * 16);

    load_stage(0, 0);
    load_stage(1, 1);
    load_stage(2, 2);

    #pragma unroll 1
    for (int st = 0; st < 16; st++) {
        if (st <= 13)      CP_WAIT(2);
        else if (st == 14) CP_WAIT(1);
        else               CP_WAIT(0);
        __syncthreads();
        uint32_t base = sb + (st % 3)*TR_STAGE;
        #pragma unroll
        for (int kc = 0; kc < 2; kc++) {
            uint32_t kb = coff + kc*32;
            uint32_t Ah[2][4];
            #pragma unroll
            for (int mt=0; mt<2; mt++)
                ldm_x4(Ah[mt], base + (uint32_t)((m0 + mt*16 + l16) * TSROW) + kb);
            #pragma unroll
            for (int np=0; np<4; np++) {
                uint32_t Bh[4];
                ldm_x4(Bh, base + TPLANE + (uint32_t)((n0 + np*16 + l16) * TSROW) + kb);
                #pragma unroll
                for (int h=0; h<2; h++) {
                    uint32_t bh[2] = {Bh[h], Bh[2+h]};
                    int nt = np*2 + h;
                    #pragma unroll
                    for (int mt=0; mt<2; mt++)
                        mma_f16(acc[mt][nt], Ah[mt], bh);
                }
            }
        }
        __syncthreads();
        if (st + 3 < 16) load_stage(st + 3, st % 3);
    }

    uint32_t* O = Ot + (size_t)cz*(NN_/2);
    #pragma unroll
    for (int mt=0; mt<2; mt++) {
        int r = i0 + m0 + mt*16 + g;
        #pragma unroll
        for (int nt=0; nt<8; nt++) {
            int cl = j0 + n0 + nt*8 + 2*tg;
            O[(size_t)r*(N_/2) + cl/2]     = pack_h2(acc[mt][nt][0], acc[mt][nt][1]);
            O[(size_t)(r+8)*(N_/2) + cl/2] = pack_h2(acc[mt][nt][2], acc[mt][nt][3]);
        }
    }
}

// ---------------------------------------------------------------------------
// out_fused: 64-ij tile, 256 thr, 3 CTAs/SM.  (unchanged from R12)
// ---------------------------------------------------------------------------
#define OF_WO   34816
#define OF_WS   69632
#define OF_SMEM 70656

__global__ __launch_bounds__(256, 3) void out_fused(
    const uint32_t* __restrict__ ot, const uint32_t* __restrict__ gate,
    const float* __restrict__ lnw, const float* __restrict__ lnb,
    const uint32_t* __restrict__ WoH,
    float* __restrict__ out)
{
    extern __shared__ char sm[];
    uint32_t sb = smem_u32(sm);
    int t = threadIdx.x, warp = t>>5, lane = t&31, g = lane>>2, tg = lane&3;
    int l16 = lane & 15;
    uint32_t coff = (uint32_t)((lane >> 4) * 16);
    int m0 = (warp & 1) * 32, n0 = (warp >> 1) * 32;
    size_t ij0 = (size_t)blockIdx.x * 64;

    #pragma unroll
    for (int i = 0; i < 4; i++) {
        int e = i*256 + t, c = e >> 3, ch = e & 7;
        cp16s(sb + (uint32_t)(c*XROW + ch*16),
              (const char*)(ot + (size_t)c*(NN_/2) + ij0/2) + ch*16);
    }
    cp_commit();
    #pragma unroll
    for (int i = 0; i < 8; i++) {
        int e = i*256 + t;
        int r = e >> 4, ch = e & 15;
        cp16s(sb + OF_WO + (uint32_t)(r*XROW + ch*16), WoH + (size_t)r*64 + ch*4);
    }
    cp_commit();

    if (t < 128) {
        ((float*)(sm + OF_WS))[t]       = lnw[t];
        ((float*)(sm + OF_WS))[128 + t] = lnb[t];
    }

    CP_WAIT(1); __syncthreads();

    {
        float* wv = (float*)(sm + OF_WS);
        int ij = t >> 2, q = t & 3;
        float y[32];
        float s1 = 0.f, s2 = 0.f;
        #pragma unroll
        for (int i = 0; i < 32; i++) {
            int c = q*32 + i;
            __half h = *(const __half*)(sm + c*XROW + ij*2);
            float v = __half2float(h);
            y[i] = v; s1 += v; s2 += v*v;
        }
        s1 += __shfl_xor_sync(~0u, s1, 1); s2 += __shfl_xor_sync(~0u, s2, 1);
        s1 += __shfl_xor_sync(~0u, s1, 2); s2 += __shfl_xor_sync(~0u, s2, 2);
        float mu  = s1 * (1.f/128.f);
        float var = s2 * (1.f/128.f) - mu*mu;
        float inv = rsqrtf(var + 1e-5f);
        __syncthreads();
        uint32_t* oh = (uint32_t*)(sm + ij*XROW);
        uint32_t* ol = (uint32_t*)(sm + XPL64 + ij*XROW);
        #pragma unroll
        for (int j = 0; j < 16; j++) {
            int c0 = q*32 + 2*j;
            float y0 = (y[2*j]   - mu) * inv * wv[c0]   + wv[128 + c0];
            float y1 = (y[2*j+1] - mu) * inv * wv[c0+1] + wv[128 + c0 + 1];
            uint2 p = pack_split(y0, y1);
            oh[q*16 + j] = p.x;
            ol[q*16 + j] = p.y;
        }
    }
    CP_WAIT(0); __syncthreads();

    float acc[2][4][4];
    #pragma unroll
    for (int mt=0; mt<2; mt++)
        #pragma unroll
        for (int nt=0; nt<4; nt++)
            #pragma unroll
            for (int q=0; q<4; q++) acc[mt][nt][q]=0.f;

    gemm64<XPL64>(sb, sb + OF_WO, acc, m0, n0, l16, coff);

    #pragma unroll
    for (int mt=0; mt<2; mt++) {
        size_t rl = ij0 + m0 + mt*16 + g;
        size_t rh = rl + 8;
        #pragma unroll
        for (int nt=0; nt<4; nt++) {
            int cl = n0 + nt*8 + 2*tg;
            __half2 glh = *(const __half2*)(gate + rl*64 + cl/2);
            __half2 ghh = *(const __half2*)(gate + rh*64 + cl/2);
            float2 gl = __half22float2(glh);
            float2 gh = __half22float2(ghh);
            *(float2*)(out + rl*C_ + cl) =
                make_float2(gl.x * acc[mt][nt][0], gl.y * acc[mt][nt][1]);
            *(float2*)(out + rh*C_ + cl) =
                make_float2(gh.x * acc[mt][nt][2], gh.y * acc[mt][nt][3]);
        }
    }
}

// ---------------------------------------------------------------------------
extern "C" void kernel_launch(void* const* d_in, const int* in_sizes, int n_in,
                              void* d_out, int out_size)
{
    const float* z      = (const float*)d_in[0];
    const float* mask   = (const float*)d_in[1];
    const float* ln_i_w = (const float*)d_in[2];
    const float* ln_i_b = (const float*)d_in[3];
    const float* ln_o_w = (const float*)d_in[4];
    const float* ln_o_b = (const float*)d_in[5];
    const float* w_pa   = (const float*)d_in[6];
    const float* w_pb   = (const float*)d_in[7];
    const float* w_ga   = (const float*)d_in[8];
    const float* w_gb   = (const float*)d_in[9];
    const float* w_g    = (const float*)d_in[10];
    const float* w_o    = (const float*)d_in[11];
    float* out = (float*)d_out;

    uint32_t *ath, *bth, *wh, *gt, *ot;
    cudaGetSymbolAddress((void**)&ath, g_ath);
    cudaGetSymbolAddress((void**)&bth, g_bth);
    cudaGetSymbolAddress((void**)&wh,  g_wh);
    cudaGetSymbolAddress((void**)&gt,  g_gt);
    cudaGetSymbolAddress((void**)&ot,  g_ot);

    cudaFuncSetAttribute(proj_fused, cudaFuncAttributeMaxDynamicSharedMemorySize, PJ_SMEM);
    cudaFuncSetAttribute(out_fused,  cudaFuncAttributeMaxDynamicSharedMemorySize, OF_SMEM);
    cudaFuncSetAttribute(tri_lm,     cudaFuncAttributeMaxDynamicSharedMemorySize, TR_SMEM);

    // weight plane order: ga=0, pa=1, gb=2, pb=3, g=4, o=5
    split_w_lm<<<dim3(32, 6), 256>>>(w_ga, w_pa, w_gb, w_pb, w_g, w_o, wh);
    // LN(z) + 5 projections fused (64-row tiles, 2 CTAs/SM)
    proj_fused<<<NN_/64, 256, PJ_SMEM>>>(z, mask, ln_i_w, ln_i_b, wh,
                                         ath, bth, gt);
    // triangle einsum (1-term fp16) -> ot fp16 c-major
    tri_lm<<<dim3(N_/128, N_/128, C_), 256, TR_SMEM>>>(ath, bth, ot);
    // transpose+LN+GEMM+gate fused (64-ij tiles, 3 CTAs/SM)
    out_fused<<<NN_/64, 256, OF_SMEM>>>(ot, gt, ln_o_w, ln_o_b,
                                        wh + 5*C_*64, out);
}

// round 15
// speedup vs baseline: 1.3354x; 1.1166x over previous
#include <cuda_runtime.h>
#include <cuda_fp16.h>
#include <cstdint>

#define N_  512
#define C_  128
#define NN_ (N_*N_)

// ---------------------------------------------------------------------------
// global scratch (fp16 planes stored as uint32 = half2 of consecutive k pair)
// ---------------------------------------------------------------------------
__device__ uint32_t g_ath[(size_t)C_*(NN_/2)];  // a hi, c-major [c][(i*512+k)/2]
__device__ uint32_t g_bth[(size_t)C_*(NN_/2)];  // b hi
__device__ uint32_t g_wh [6*C_*64];             // weight hi planes [which][n][k/2]
__device__ uint32_t g_gt [(size_t)NN_*64];      // gate fp16 half2 [row][c/2]
__device__ uint32_t g_ot [(size_t)C_*(NN_/2)];  // einsum out fp16 half2, c-major

// ---------------------------------------------------------------------------
__device__ __forceinline__ float sigf(float x) { return 1.f / (1.f + __expf(-x)); }

__device__ __forceinline__ uint2 pack_split(float x0, float x1) {
    __half2 hh = __floats2half2_rn(x0, x1);
    float r0 = x0 - __half2float(__low2half(hh));
    float r1 = x1 - __half2float(__high2half(hh));
    __half2 ll = __floats2half2_rn(r0, r1);
    uint2 out;
    out.x = *reinterpret_cast<uint32_t*>(&hh);
    out.y = *reinterpret_cast<uint32_t*>(&ll);
    return out;
}
__device__ __forceinline__ uint32_t pack_h2(float x0, float x1) {
    __half2 hh = __floats2half2_rn(x0, x1);
    return *reinterpret_cast<uint32_t*>(&hh);
}

__device__ __forceinline__ void mma_f16(float* c, const uint32_t* a, const uint32_t* b) {
    asm volatile(
        "mma.sync.aligned.m16n8k16.row.col.f32.f16.f16.f32 "
        "{%0,%1,%2,%3},{%4,%5,%6,%7},{%8,%9},{%0,%1,%2,%3};\n"
        : "+f"(c[0]), "+f"(c[1]), "+f"(c[2]), "+f"(c[3])
        : "r"(a[0]), "r"(a[1]), "r"(a[2]), "r"(a[3]), "r"(b[0]), "r"(b[1]));
}

__device__ __forceinline__ uint32_t smem_u32(const void* p) {
    uint32_t a;
    asm("{ .reg .u64 t; cvta.to.shared.u64 t, %1; cvt.u32.u64 %0, t; }" : "=r"(a) : "l"(p));
    return a;
}
__device__ __forceinline__ void cp16s(uint32_t saddr, const void* g) {
    asm volatile("cp.async.cg.shared.global [%0], [%1], 16;\n" :: "r"(saddr), "l"(g));
}
__device__ __forceinline__ void cp_commit() { asm volatile("cp.async.commit_group;\n"); }
#define CP_WAIT(n) asm volatile("cp.async.wait_group %0;\n" :: "n"(n))

__device__ __forceinline__ void ldm_x4(uint32_t* r, uint32_t addr) {
    asm volatile("ldmatrix.sync.aligned.m8n8.x4.shared.b16 {%0,%1,%2,%3}, [%4];"
        : "=r"(r[0]), "=r"(r[1]), "=r"(r[2]), "=r"(r[3]) : "r"(addr));
}

// ---------------------------------------------------------------------------
// 64xN x128 GEMM body. TERMS=2: X hi+lo planes; TERMS=1: X hi only.
// X planes at xb (hi) / xb+XPLA (lo); W hi plane at wb (128 rows, 272B stride).
// 8 warps, warp tile 32x32 (2M x 4N).
// ---------------------------------------------------------------------------
#define XROW 272
#define XPL64 17408

template<int XPLA, int TERMS>
__device__ __forceinline__ void gemm64(uint32_t xb, uint32_t wb, float acc[2][4][4],
                                       int m0, int n0, int l16, uint32_t coff)
{
    #pragma unroll
    for (int kc = 0; kc < 8; kc++) {
        uint32_t kb = coff + kc*32;
        uint32_t Ah[2][4], Al[2][4];
        #pragma unroll
        for (int mt = 0; mt < 2; mt++) {
            uint32_t ar = (uint32_t)((m0 + mt*16 + l16) * XROW) + kb;
            ldm_x4(Ah[mt], xb + ar);
            if (TERMS == 2) ldm_x4(Al[mt], xb + XPLA + ar);
        }
        #pragma unroll
        for (int np = 0; np < 2; np++) {
            uint32_t br = (uint32_t)((n0 + np*16 + l16) * XROW) + kb;
            uint32_t Bh[4];
            ldm_x4(Bh, wb + br);
            #pragma unroll
            for (int h = 0; h < 2; h++) {
                uint32_t bh[2] = {Bh[h], Bh[2+h]};
                int nt = np*2 + h;
                #pragma unroll
                for (int mt = 0; mt < 2; mt++) {
                    mma_f16(acc[mt][nt], Ah[mt], bh);
                    if (TERMS == 2) mma_f16(acc[mt][nt], Al[mt], bh);
                }
            }
        }
    }
}

// ---------------------------------------------------------------------------
// weight split -> hi planes.  order: ga=0, pa=1, gb=2, pb=3, g=4, o=5
// ---------------------------------------------------------------------------
__global__ __launch_bounds__(256) void split_w_lm(
    const float* __restrict__ w0, const float* __restrict__ w1,
    const float* __restrict__ w2, const float* __restrict__ w3,
    const float* __restrict__ w4, const float* __restrict__ w5,
    uint32_t* __restrict__ wh)
{
    int which = blockIdx.y;
    const float* w = which==0?w0 : which==1?w1 : which==2?w2 :
                     which==3?w3 : which==4?w4 : w5;
    int e = blockIdx.x*256 + threadIdx.x;
    int n = e >> 6, kk = e & 63;
    wh[which*C_*64 + e] = pack_h2(w[n*C_ + 2*kk], w[n*C_ + 2*kk + 1]);
}

// ---------------------------------------------------------------------------
// proj_fused: 64-row tile, 256 thr, 2 CTAs/SM. 1-TERM X (hi plane only).
// ---------------------------------------------------------------------------
#define PJ_B0   34816
#define PJ_B1   69632
#define PJ_WS   104448
#define PJ_SMEM 105472

__global__ __launch_bounds__(256, 2) void proj_fused(
    const float* __restrict__ z, const float* __restrict__ mask,
    const float* __restrict__ lnw, const float* __restrict__ lnb,
    const uint32_t* __restrict__ WH,
    uint32_t* __restrict__ aH, uint32_t* __restrict__ bH,
    uint32_t* __restrict__ gate)
{
    extern __shared__ char sm[];
    uint32_t sb = smem_u32(sm);
    int t = threadIdx.x, warp = t>>5, lane = t&31, g = lane>>2, tg = lane&3;
    int l16 = lane & 15;
    uint32_t coff = (uint32_t)((lane >> 4) * 16);
    int m0 = (warp & 1) * 32, n0 = (warp >> 1) * 32;
    size_t row0 = (size_t)blockIdx.x * 64;

    auto loadW = [&](int which, uint32_t dst) {
        const uint32_t* srcH = WH + which*8192;
        #pragma unroll
        for (int i = 0; i < 8; i++) {
            int e = i*256 + t;
            int r = e >> 4, ch = e & 15;
            cp16s(dst + (uint32_t)(r*XROW + ch*16), srcH + (size_t)r*64 + ch*4);
        }
        cp_commit();
    };

    {
        const char* zp = (const char*)(z + row0*C_);
        #pragma unroll
        for (int i = 0; i < 8; i++) {
            int e = i*256 + t, r = e >> 5, c4 = e & 31;
            cp16s(sb + (uint32_t)(r*528 + c4*16), zp + (size_t)r*512 + c4*16);
        }
        cp_commit();
    }
    loadW(0, sb + PJ_B0);   // ga
    loadW(1, sb + PJ_B1);   // pa

    if (t < 128) {
        ((float*)(sm + PJ_WS))[t]       = lnw[t];
        ((float*)(sm + PJ_WS))[128 + t] = lnb[t];
    }

    CP_WAIT(2);
    __syncthreads();

    // LN in place over X region (hi plane only)
    {
        float* s  = (float*)sm;
        float* wv = (float*)(sm + PJ_WS);
        int r = t >> 2, q = t & 3;
        float y[32];
        float s1 = 0.f, s2 = 0.f;
        #pragma unroll
        for (int i = 0; i < 32; i++) {
            float v = s[r*132 + q*32 + i];
            y[i] = v; s1 += v; s2 += v*v;
        }
        s1 += __shfl_xor_sync(~0u, s1, 1); s2 += __shfl_xor_sync(~0u, s2, 1);
        s1 += __shfl_xor_sync(~0u, s1, 2); s2 += __shfl_xor_sync(~0u, s2, 2);
        float mu  = s1 * (1.f/128.f);
        float var = s2 * (1.f/128.f) - mu*mu;
        float inv = rsqrtf(var + 1e-5f);
        __syncthreads();
        uint32_t* xh = (uint32_t*)(sm + r*XROW);
        #pragma unroll
        for (int j = 0; j < 16; j++) {
            int c0 = q*32 + 2*j;
            float y0 = (y[2*j]   - mu) * inv * wv[c0]   + wv[128 + c0];
            float y1 = (y[2*j+1] - mu) * inv * wv[c0+1] + wv[128 + c0 + 1];
            xh[q*16 + j] = pack_h2(y0, y1);
        }
    }
    __syncthreads();

    float acc1[2][4][4], acc2[2][4][4];
    auto zacc = [&]() {
        #pragma unroll
        for (int mt = 0; mt < 2; mt++)
            #pragma unroll
            for (int nt = 0; nt < 4; nt++)
                #pragma unroll
                for (int q = 0; q < 4; q++) { acc1[mt][nt][q] = 0.f; acc2[mt][nt][q] = 0.f; }
    };

    auto epi_ab = [&](uint32_t* Yh) {
        __syncthreads();
        float* so = (float*)(sm + PJ_B0);
        #pragma unroll
        for (int mt = 0; mt < 2; mt++) {
            int rl = m0 + mt*16 + g, rh = rl + 8;
            float ml = mask[row0 + rl], mh = mask[row0 + rh];
            #pragma unroll
            for (int nt = 0; nt < 4; nt++) {
                int cl = n0 + nt*8 + 2*tg;
                so[rl*132 + cl]     = ml * sigf(acc1[mt][nt][0]) * acc2[mt][nt][0];
                so[rl*132 + cl + 1] = ml * sigf(acc1[mt][nt][1]) * acc2[mt][nt][1];
                so[rh*132 + cl]     = mh * sigf(acc1[mt][nt][2]) * acc2[mt][nt][2];
                so[rh*132 + cl + 1] = mh * sigf(acc1[mt][nt][3]) * acc2[mt][nt][3];
            }
        }
        __syncthreads();
        int c = t >> 1, p0 = (t & 1) * 16;
        size_t ub = (size_t)c * (NN_/2) + row0/2;
        #pragma unroll
        for (int p = 0; p < 16; p++) {
            int pr = p0 + p;
            Yh[ub + pr] = pack_h2(so[(2*pr)*132 + c], so[(2*pr+1)*132 + c]);
        }
        __syncthreads();
    };

    // ---- ga,pa -> a ----
    zacc();
    CP_WAIT(1); __syncthreads();
    gemm64<XPL64,1>(sb, sb + PJ_B0, acc1, m0, n0, l16, coff);    // ga
    CP_WAIT(0); __syncthreads();
    gemm64<XPL64,1>(sb, sb + PJ_B1, acc2, m0, n0, l16, coff);    // pa
    __syncthreads();
    loadW(2, sb + PJ_B1);          // gb
    epi_ab(aH);
    loadW(3, sb + PJ_B0);          // pb
    // ---- gb,pb -> b ----
    zacc();
    CP_WAIT(1); __syncthreads();
    gemm64<XPL64,1>(sb, sb + PJ_B1, acc1, m0, n0, l16, coff);    // gb
    CP_WAIT(0); __syncthreads();
    gemm64<XPL64,1>(sb, sb + PJ_B0, acc2, m0, n0, l16, coff);    // pb
    __syncthreads();
    loadW(4, sb + PJ_B1);          // wg
    epi_ab(bH);
    // ---- wg -> gate (fp16 packed) ----
    zacc();
    CP_WAIT(0); __syncthreads();
    gemm64<XPL64,1>(sb, sb + PJ_B1, acc1, m0, n0, l16, coff);    // wg

    #pragma unroll
    for (int mt = 0; mt < 2; mt++) {
        size_t rl = row0 + m0 + mt*16 + g;
        size_t rh = rl + 8;
        #pragma unroll
        for (int nt = 0; nt < 4; nt++) {
            int cl = n0 + nt*8 + 2*tg;
            gate[rl*64 + cl/2] = pack_h2(sigf(acc1[mt][nt][0]), sigf(acc1[mt][nt][1]));
            gate[rh*64 + cl/2] = pack_h2(sigf(acc1[mt][nt][2]), sigf(acc1[mt][nt][3]));
        }
    }
}

// ---------------------------------------------------------------------------
// tri: per channel cz, 128x128 tile, K=512 in 16 stages of k32.
// 1-term fp16, 256 thr, 8 warps (4M x 2N), 2 CTAs/SM, 3-slot ring. (R14)
// ---------------------------------------------------------------------------
#define TSROW 80
#define TPLANE (128*TSROW)
#define TR_STAGE (2*TPLANE)
#define TR_SMEM  (3*TR_STAGE)

__global__ __launch_bounds__(256, 2) void tri_lm(
    const uint32_t* __restrict__ AhG, const uint32_t* __restrict__ BhG,
    uint32_t* __restrict__ Ot)
{
    extern __shared__ char smraw[];
    uint32_t sb = smem_u32(smraw);
    int t = threadIdx.x, warp = t>>5, lane = t&31, g = lane>>2, tg = lane&3;
    int j0 = blockIdx.x * 128, i0 = blockIdx.y * 128, cz = blockIdx.z;
    int m0 = (warp & 3) * 32, n0 = (warp >> 2) * 64;

    size_t cb = (size_t)cz * (NN_/2);
    const char* p0 = (const char*)(AhG + cb + (size_t)i0*256);
    const char* p2 = (const char*)(BhG + cb + (size_t)j0*256);

    auto load_stage = [&](int st, int slot) {
        uint32_t base = sb + slot*TR_STAGE;
        #pragma unroll
        for (int i = 0; i < 4; i++) {
            int e = i*256 + t;
            int pl = e >> 9;
            int w_ = e & 511;
            int r = w_ >> 2, ch = (w_ & 3) * 16;
            const char* src = pl ? p2 : p0;
            cp16s(base + (uint32_t)(pl*TPLANE + r*TSROW + ch),
                  src + (size_t)r*1024 + st*64 + ch);
        }
        cp_commit();
    };

    float acc[2][8][4];
    #pragma unroll
    for (int mt=0; mt<2; mt++)
        #pragma unroll
        for (int nt=0; nt<8; nt++)
            #pragma unroll
            for (int q=0; q<4; q++) acc[mt][nt][q]=0.f;

    int l16 = lane & 15;
    uint32_t coff = (uint32_t)((lane >> 4) * 16);

    load_stage(0, 0);
    load_stage(1, 1);
    load_stage(2, 2);

    #pragma unroll 1
    for (int st = 0; st < 16; st++) {
        if (st <= 13)      CP_WAIT(2);
        else if (st == 14) CP_WAIT(1);
        else               CP_WAIT(0);
        __syncthreads();
        uint32_t base = sb + (st % 3)*TR_STAGE;
        #pragma unroll
        for (int kc = 0; kc < 2; kc++) {
            uint32_t kb = coff + kc*32;
            uint32_t Ah[2][4];
            #pragma unroll
            for (int mt=0; mt<2; mt++)
                ldm_x4(Ah[mt], base + (uint32_t)((m0 + mt*16 + l16) * TSROW) + kb);
            #pragma unroll
            for (int np=0; np<4; np++) {
                uint32_t Bh[4];
                ldm_x4(Bh, base + TPLANE + (uint32_t)((n0 + np*16 + l16) * TSROW) + kb);
                #pragma unroll
                for (int h=0; h<2; h++) {
                    uint32_t bh[2] = {Bh[h], Bh[2+h]};
                    int nt = np*2 + h;
                    #pragma unroll
                    for (int mt=0; mt<2; mt++)
                        mma_f16(acc[mt][nt], Ah[mt], bh);
                }
            }
        }
        __syncthreads();
        if (st + 3 < 16) load_stage(st + 3, st % 3);
    }

    uint32_t* O = Ot + (size_t)cz*(NN_/2);
    #pragma unroll
    for (int mt=0; mt<2; mt++) {
        int r = i0 + m0 + mt*16 + g;
        #pragma unroll
        for (int nt=0; nt<8; nt++) {
            int cl = j0 + n0 + nt*8 + 2*tg;
            O[(size_t)r*(N_/2) + cl/2]     = pack_h2(acc[mt][nt][0], acc[mt][nt][1]);
            O[(size_t)(r+8)*(N_/2) + cl/2] = pack_h2(acc[mt][nt][2], acc[mt][nt][3]);
        }
    }
}

// ---------------------------------------------------------------------------
// out_fused: 64-ij tile, 256 thr, 3 CTAs/SM. 2-term X (unchanged from R12).
// ---------------------------------------------------------------------------
#define OF_WO   34816
#define OF_WS   69632
#define OF_SMEM 70656

__global__ __launch_bounds__(256, 3) void out_fused(
    const uint32_t* __restrict__ ot, const uint32_t* __restrict__ gate,
    const float* __restrict__ lnw, const float* __restrict__ lnb,
    const uint32_t* __restrict__ WoH,
    float* __restrict__ out)
{
    extern __shared__ char sm[];
    uint32_t sb = smem_u32(sm);
    int t = threadIdx.x, warp = t>>5, lane = t&31, g = lane>>2, tg = lane&3;
    int l16 = lane & 15;
    uint32_t coff = (uint32_t)((lane >> 4) * 16);
    int m0 = (warp & 1) * 32, n0 = (warp >> 1) * 32;
    size_t ij0 = (size_t)blockIdx.x * 64;

    #pragma unroll
    for (int i = 0; i < 4; i++) {
        int e = i*256 + t, c = e >> 3, ch = e & 7;
        cp16s(sb + (uint32_t)(c*XROW + ch*16),
              (const char*)(ot + (size_t)c*(NN_/2) + ij0/2) + ch*16);
    }
    cp_commit();
    #pragma unroll
    for (int i = 0; i < 8; i++) {
        int e = i*256 + t;
        int r = e >> 4, ch = e & 15;
        cp16s(sb + OF_WO + (uint32_t)(r*XROW + ch*16), WoH + (size_t)r*64 + ch*4);
    }
    cp_commit();

    if (t < 128) {
        ((float*)(sm + OF_WS))[t]       = lnw[t];
        ((float*)(sm + OF_WS))[128 + t] = lnb[t];
    }

    CP_WAIT(1); __syncthreads();

    {
        float* wv = (float*)(sm + OF_WS);
        int ij = t >> 2, q = t & 3;
        float y[32];
        float s1 = 0.f, s2 = 0.f;
        #pragma unroll
        for (int i = 0; i < 32; i++) {
            int c = q*32 + i;
            __half h = *(const __half*)(sm + c*XROW + ij*2);
            float v = __half2float(h);
            y[i] = v; s1 += v; s2 += v*v;
        }
        s1 += __shfl_xor_sync(~0u, s1, 1); s2 += __shfl_xor_sync(~0u, s2, 1);
        s1 += __shfl_xor_sync(~0u, s1, 2); s2 += __shfl_xor_sync(~0u, s2, 2);
        float mu  = s1 * (1.f/128.f);
        float var = s2 * (1.f/128.f) - mu*mu;
        float inv = rsqrtf(var + 1e-5f);
        __syncthreads();
        uint32_t* oh = (uint32_t*)(sm + ij*XROW);
        uint32_t* ol = (uint32_t*)(sm + XPL64 + ij*XROW);
        #pragma unroll
        for (int j = 0; j < 16; j++) {
            int c0 = q*32 + 2*j;
            float y0 = (y[2*j]   - mu) * inv * wv[c0]   + wv[128 + c0];
            float y1 = (y[2*j+1] - mu) * inv * wv[c0+1] + wv[128 + c0 + 1];
            uint2 p = pack_split(y0, y1);
            oh[q*16 + j] = p.x;
            ol[q*16 + j] = p.y;
        }
    }
    CP_WAIT(0); __syncthreads();

    float acc[2][4][4];
    #pragma unroll
    for (int mt=0; mt<2; mt++)
        #pragma unroll
        for (int nt=0; nt<4; nt++)
            #pragma unroll
            for (int q=0; q<4; q++) acc[mt][nt][q]=0.f;

    gemm64<XPL64,2>(sb, sb + OF_WO, acc, m0, n0, l16, coff);

    #pragma unroll
    for (int mt=0; mt<2; mt++) {
        size_t rl = ij0 + m0 + mt*16 + g;
        size_t rh = rl + 8;
        #pragma unroll
        for (int nt=0; nt<4; nt++) {
            int cl = n0 + nt*8 + 2*tg;
            __half2 glh = *(const __half2*)(gate + rl*64 + cl/2);
            __half2 ghh = *(const __half2*)(gate + rh*64 + cl/2);
            float2 gl = __half22float2(glh);
            float2 gh = __half22float2(ghh);
            *(float2*)(out + rl*C_ + cl) =
                make_float2(gl.x * acc[mt][nt][0], gl.y * acc[mt][nt][1]);
            *(float2*)(out + rh*C_ + cl) =
                make_float2(gh.x * acc[mt][nt][2], gh.y * acc[mt][nt][3]);
        }
    }
}

// ---------------------------------------------------------------------------
extern "C" void kernel_launch(void* const* d_in, const int* in_sizes, int n_in,
                              void* d_out, int out_size)
{
    const float* z      = (const float*)d_in[0];
    const float* mask   = (const float*)d_in[1];
    const float* ln_i_w = (const float*)d_in[2];
    const float* ln_i_b = (const float*)d_in[3];
    const float* ln_o_w = (const float*)d_in[4];
    const float* ln_o_b = (const float*)d_in[5];
    const float* w_pa   = (const float*)d_in[6];
    const float* w_pb   = (const float*)d_in[7];
    const float* w_ga   = (const float*)d_in[8];
    const float* w_gb   = (const float*)d_in[9];
    const float* w_g    = (const float*)d_in[10];
    const float* w_o    = (const float*)d_in[11];
    float* out = (float*)d_out;

    uint32_t *ath, *bth, *wh, *gt, *ot;
    cudaGetSymbolAddress((void**)&ath, g_ath);
    cudaGetSymbolAddress((void**)&bth, g_bth);
    cudaGetSymbolAddress((void**)&wh,  g_wh);
    cudaGetSymbolAddress((void**)&gt,  g_gt);
    cudaGetSymbolAddress((void**)&ot,  g_ot);

    cudaFuncSetAttribute(proj_fused, cudaFuncAttributeMaxDynamicSharedMemorySize, PJ_SMEM);
    cudaFuncSetAttribute(out_fused,  cudaFuncAttributeMaxDynamicSharedMemorySize, OF_SMEM);
    cudaFuncSetAttribute(tri_lm,     cudaFuncAttributeMaxDynamicSharedMemorySize, TR_SMEM);

    // weight plane order: ga=0, pa=1, gb=2, pb=3, g=4, o=5
    split_w_lm<<<dim3(32, 6), 256>>>(w_ga, w_pa, w_gb, w_pb, w_g, w_o, wh);
    // LN(z) + 5 projections fused (1-term fp16, 64-row tiles, 2 CTAs/SM)
    proj_fused<<<NN_/64, 256, PJ_SMEM>>>(z, mask, ln_i_w, ln_i_b, wh,
                                         ath, bth, gt);
    // triangle einsum (1-term fp16) -> ot fp16 c-major
    tri_lm<<<dim3(N_/128, N_/128, C_), 256, TR_SMEM>>>(ath, bth, ot);
    // transpose+LN+GEMM+gate fused (2-term, 64-ij tiles, 3 CTAs/SM)
    out_fused<<<NN_/64, 256, OF_SMEM>>>(ot, gt, ln_o_w, ln_o_b,
                                        wh + 5*C_*64, out);
}

// round 16
// speedup vs baseline: 1.3554x; 1.0150x over previous
#include <cuda_runtime.h>
#include <cuda_fp16.h>
#include <cstdint>

#define N_  512
#define C_  128
#define NN_ (N_*N_)

// ---------------------------------------------------------------------------
// global scratch (fp16 planes stored as uint32 = half2 of consecutive k pair)
// ---------------------------------------------------------------------------
__device__ uint32_t g_ath[(size_t)C_*(NN_/2)];  // a hi, c-major [c][(i*512+k)/2]
__device__ uint32_t g_bth[(size_t)C_*(NN_/2)];  // b hi
__device__ uint32_t g_wh [6*C_*64];             // weight hi planes [which][n][k/2]
__device__ uint32_t g_gt [(size_t)NN_*64];      // gate fp16 half2 [row][c/2]
__device__ uint32_t g_ot [(size_t)C_*(NN_/2)];  // einsum out fp16 half2, c-major

// ---------------------------------------------------------------------------
__device__ __forceinline__ float sigf(float x) { return 1.f / (1.f + __expf(-x)); }

__device__ __forceinline__ uint32_t pack_h2(float x0, float x1) {
    __half2 hh = __floats2half2_rn(x0, x1);
    return *reinterpret_cast<uint32_t*>(&hh);
}

__device__ __forceinline__ void mma_f16(float* c, const uint32_t* a, const uint32_t* b) {
    asm volatile(
        "mma.sync.aligned.m16n8k16.row.col.f32.f16.f16.f32 "
        "{%0,%1,%2,%3},{%4,%5,%6,%7},{%8,%9},{%0,%1,%2,%3};\n"
        : "+f"(c[0]), "+f"(c[1]), "+f"(c[2]), "+f"(c[3])
        : "r"(a[0]), "r"(a[1]), "r"(a[2]), "r"(a[3]), "r"(b[0]), "r"(b[1]));
}

__device__ __forceinline__ uint32_t smem_u32(const void* p) {
    uint32_t a;
    asm("{ .reg .u64 t; cvta.to.shared.u64 t, %1; cvt.u32.u64 %0, t; }" : "=r"(a) : "l"(p));
    return a;
}
__device__ __forceinline__ void cp16s(uint32_t saddr, const void* g) {
    asm volatile("cp.async.cg.shared.global [%0], [%1], 16;\n" :: "r"(saddr), "l"(g));
}
__device__ __forceinline__ void cp_commit() { asm volatile("cp.async.commit_group;\n"); }
#define CP_WAIT(n) asm volatile("cp.async.wait_group %0;\n" :: "n"(n))

__device__ __forceinline__ void ldm_x4(uint32_t* r, uint32_t addr) {
    asm volatile("ldmatrix.sync.aligned.m8n8.x4.shared.b16 {%0,%1,%2,%3}, [%4];"
        : "=r"(r[0]), "=r"(r[1]), "=r"(r[2]), "=r"(r[3]) : "r"(addr));
}

// ---------------------------------------------------------------------------
// 64xN x128 GEMM body, 1-term fp16. X hi plane at xb (64 rows, 272B stride);
// W hi plane at wb (128 rows, 272B stride). 8 warps, warp tile 32x32 (2M x 4N).
// ---------------------------------------------------------------------------
#define XROW 272

__device__ __forceinline__ void gemm64(uint32_t xb, uint32_t wb, float acc[2][4][4],
                                       int m0, int n0, int l16, uint32_t coff)
{
    #pragma unroll
    for (int kc = 0; kc < 8; kc++) {
        uint32_t kb = coff + kc*32;
        uint32_t Ah[2][4];
        #pragma unroll
        for (int mt = 0; mt < 2; mt++)
            ldm_x4(Ah[mt], xb + (uint32_t)((m0 + mt*16 + l16) * XROW) + kb);
        #pragma unroll
        for (int np = 0; np < 2; np++) {
            uint32_t Bh[4];
            ldm_x4(Bh, wb + (uint32_t)((n0 + np*16 + l16) * XROW) + kb);
            #pragma unroll
            for (int h = 0; h < 2; h++) {
                uint32_t bh[2] = {Bh[h], Bh[2+h]};
                int nt = np*2 + h;
                #pragma unroll
                for (int mt = 0; mt < 2; mt++)
                    mma_f16(acc[mt][nt], Ah[mt], bh);
            }
        }
    }
}

// ---------------------------------------------------------------------------
// weight split -> hi planes.  order: ga=0, pa=1, gb=2, pb=3, g=4, o=5
// ---------------------------------------------------------------------------
__global__ __launch_bounds__(256) void split_w_lm(
    const float* __restrict__ w0, const float* __restrict__ w1,
    const float* __restrict__ w2, const float* __restrict__ w3,
    const float* __restrict__ w4, const float* __restrict__ w5,
    uint32_t* __restrict__ wh)
{
    int which = blockIdx.y;
    const float* w = which==0?w0 : which==1?w1 : which==2?w2 :
                     which==3?w3 : which==4?w4 : w5;
    int e = blockIdx.x*256 + threadIdx.x;
    int n = e >> 6, kk = e & 63;
    wh[which*C_*64 + e] = pack_h2(w[n*C_ + 2*kk], w[n*C_ + 2*kk + 1]);
}

// ---------------------------------------------------------------------------
// proj_fused: 64-row tile, 256 thr, 2 CTAs/SM. 1-term X. (R15 verified)
// smem: X hi [0,17408)+pad | B0 [34816,69632) | B1 [69632,104448) | ws 1KB
// ---------------------------------------------------------------------------
#define PJ_B0   34816
#define PJ_B1   69632
#define PJ_WS   104448
#define PJ_SMEM 105472

__global__ __launch_bounds__(256, 2) void proj_fused(
    const float* __restrict__ z, const float* __restrict__ mask,
    const float* __restrict__ lnw, const float* __restrict__ lnb,
    const uint32_t* __restrict__ WH,
    uint32_t* __restrict__ aH, uint32_t* __restrict__ bH,
    uint32_t* __restrict__ gate)
{
    extern __shared__ char sm[];
    uint32_t sb = smem_u32(sm);
    int t = threadIdx.x, warp = t>>5, lane = t&31, g = lane>>2, tg = lane&3;
    int l16 = lane & 15;
    uint32_t coff = (uint32_t)((lane >> 4) * 16);
    int m0 = (warp & 1) * 32, n0 = (warp >> 1) * 32;
    size_t row0 = (size_t)blockIdx.x * 64;

    auto loadW = [&](int which, uint32_t dst) {
        const uint32_t* srcH = WH + which*8192;
        #pragma unroll
        for (int i = 0; i < 8; i++) {
            int e = i*256 + t;
            int r = e >> 4, ch = e & 15;
            cp16s(dst + (uint32_t)(r*XROW + ch*16), srcH + (size_t)r*64 + ch*4);
        }
        cp_commit();
    };

    {
        const char* zp = (const char*)(z + row0*C_);
        #pragma unroll
        for (int i = 0; i < 8; i++) {
            int e = i*256 + t, r = e >> 5, c4 = e & 31;
            cp16s(sb + (uint32_t)(r*528 + c4*16), zp + (size_t)r*512 + c4*16);
        }
        cp_commit();
    }
    loadW(0, sb + PJ_B0);   // ga
    loadW(1, sb + PJ_B1);   // pa

    if (t < 128) {
        ((float*)(sm + PJ_WS))[t]       = lnw[t];
        ((float*)(sm + PJ_WS))[128 + t] = lnb[t];
    }

    CP_WAIT(2);
    __syncthreads();

    // LN in place over X region (hi plane only)
    {
        float* s  = (float*)sm;
        float* wv = (float*)(sm + PJ_WS);
        int r = t >> 2, q = t & 3;
        float y[32];
        float s1 = 0.f, s2 = 0.f;
        #pragma unroll
        for (int i = 0; i < 32; i++) {
            float v = s[r*132 + q*32 + i];
            y[i] = v; s1 += v; s2 += v*v;
        }
        s1 += __shfl_xor_sync(~0u, s1, 1); s2 += __shfl_xor_sync(~0u, s2, 1);
        s1 += __shfl_xor_sync(~0u, s1, 2); s2 += __shfl_xor_sync(~0u, s2, 2);
        float mu  = s1 * (1.f/128.f);
        float var = s2 * (1.f/128.f) - mu*mu;
        float inv = rsqrtf(var + 1e-5f);
        __syncthreads();
        uint32_t* xh = (uint32_t*)(sm + r*XROW);
        #pragma unroll
        for (int j = 0; j < 16; j++) {
            int c0 = q*32 + 2*j;
            float y0 = (y[2*j]   - mu) * inv * wv[c0]   + wv[128 + c0];
            float y1 = (y[2*j+1] - mu) * inv * wv[c0+1] + wv[128 + c0 + 1];
            xh[q*16 + j] = pack_h2(y0, y1);
        }
    }
    __syncthreads();

    float acc1[2][4][4], acc2[2][4][4];
    auto zacc = [&]() {
        #pragma unroll
        for (int mt = 0; mt < 2; mt++)
            #pragma unroll
            for (int nt = 0; nt < 4; nt++)
                #pragma unroll
                for (int q = 0; q < 4; q++) { acc1[mt][nt][q] = 0.f; acc2[mt][nt][q] = 0.f; }
    };

    auto epi_ab = [&](uint32_t* Yh) {
        __syncthreads();
        float* so = (float*)(sm + PJ_B0);
        #pragma unroll
        for (int mt = 0; mt < 2; mt++) {
            int rl = m0 + mt*16 + g, rh = rl + 8;
            float ml = mask[row0 + rl], mh = mask[row0 + rh];
            #pragma unroll
            for (int nt = 0; nt < 4; nt++) {
                int cl = n0 + nt*8 + 2*tg;
                so[rl*132 + cl]     = ml * sigf(acc1[mt][nt][0]) * acc2[mt][nt][0];
                so[rl*132 + cl + 1] = ml * sigf(acc1[mt][nt][1]) * acc2[mt][nt][1];
                so[rh*132 + cl]     = mh * sigf(acc1[mt][nt][2]) * acc2[mt][nt][2];
                so[rh*132 + cl + 1] = mh * sigf(acc1[mt][nt][3]) * acc2[mt][nt][3];
            }
        }
        __syncthreads();
        int c = t >> 1, p0 = (t & 1) * 16;
        size_t ub = (size_t)c * (NN_/2) + row0/2;
        #pragma unroll
        for (int p = 0; p < 16; p++) {
            int pr = p0 + p;
            Yh[ub + pr] = pack_h2(so[(2*pr)*132 + c], so[(2*pr+1)*132 + c]);
        }
        __syncthreads();
    };

    // ---- ga,pa -> a ----
    zacc();
    CP_WAIT(1); __syncthreads();
    gemm64(sb, sb + PJ_B0, acc1, m0, n0, l16, coff);    // ga
    CP_WAIT(0); __syncthreads();
    gemm64(sb, sb + PJ_B1, acc2, m0, n0, l16, coff);    // pa
    __syncthreads();
    loadW(2, sb + PJ_B1);          // gb
    epi_ab(aH);
    loadW(3, sb + PJ_B0);          // pb
    // ---- gb,pb -> b ----
    zacc();
    CP_WAIT(1); __syncthreads();
    gemm64(sb, sb + PJ_B1, acc1, m0, n0, l16, coff);    // gb
    CP_WAIT(0); __syncthreads();
    gemm64(sb, sb + PJ_B0, acc2, m0, n0, l16, coff);    // pb
    __syncthreads();
    loadW(4, sb + PJ_B1);          // wg
    epi_ab(bH);
    // ---- wg -> gate (fp16 packed) ----
    zacc();
    CP_WAIT(0); __syncthreads();
    gemm64(sb, sb + PJ_B1, acc1, m0, n0, l16, coff);    // wg

    #pragma unroll
    for (int mt = 0; mt < 2; mt++) {
        size_t rl = row0 + m0 + mt*16 + g;
        size_t rh = rl + 8;
        #pragma unroll
        for (int nt = 0; nt < 4; nt++) {
            int cl = n0 + nt*8 + 2*tg;
            gate[rl*64 + cl/2] = pack_h2(sigf(acc1[mt][nt][0]), sigf(acc1[mt][nt][1]));
            gate[rh*64 + cl/2] = pack_h2(sigf(acc1[mt][nt][2]), sigf(acc1[mt][nt][3]));
        }
    }
}

// ---------------------------------------------------------------------------
// tri: per channel cz, 128x128 tile, K=512 in 16 stages of k32.
// 1-term fp16, 256 thr, 8 warps (4M x 2N), 2 CTAs/SM, 3-slot ring. (R14 verified)
// ---------------------------------------------------------------------------
#define TSROW 80
#define TPLANE (128*TSROW)
#define TR_STAGE (2*TPLANE)
#define TR_SMEM  (3*TR_STAGE)

__global__ __launch_bounds__(256, 2) void tri_lm(
    const uint32_t* __restrict__ AhG, const uint32_t* __restrict__ BhG,
    uint32_t* __restrict__ Ot)
{
    extern __shared__ char smraw[];
    uint32_t sb = smem_u32(smraw);
    int t = threadIdx.x, warp = t>>5, lane = t&31, g = lane>>2, tg = lane&3;
    int j0 = blockIdx.x * 128, i0 = blockIdx.y * 128, cz = blockIdx.z;
    int m0 = (warp & 3) * 32, n0 = (warp >> 2) * 64;

    size_t cb = (size_t)cz * (NN_/2);
    const char* p0 = (const char*)(AhG + cb + (size_t)i0*256);
    const char* p2 = (const char*)(BhG + cb + (size_t)j0*256);

    auto load_stage = [&](int st, int slot) {
        uint32_t base = sb + slot*TR_STAGE;
        #pragma unroll
        for (int i = 0; i < 4; i++) {
            int e = i*256 + t;
            int pl = e >> 9;
            int w_ = e & 511;
            int r = w_ >> 2, ch = (w_ & 3) * 16;
            const char* src = pl ? p2 : p0;
            cp16s(base + (uint32_t)(pl*TPLANE + r*TSROW + ch),
                  src + (size_t)r*1024 + st*64 + ch);
        }
        cp_commit();
    };

    float acc[2][8][4];
    #pragma unroll
    for (int mt=0; mt<2; mt++)
        #pragma unroll
        for (int nt=0; nt<8; nt++)
            #pragma unroll
            for (int q=0; q<4; q++) acc[mt][nt][q]=0.f;

    int l16 = lane & 15;
    uint32_t coff = (uint32_t)((lane >> 4) * 16);

    load_stage(0, 0);
    load_stage(1, 1);
    load_stage(2, 2);

    #pragma unroll 1
    for (int st = 0; st < 16; st++) {
        if (st <= 13)      CP_WAIT(2);
        else if (st == 14) CP_WAIT(1);
        else               CP_WAIT(0);
        __syncthreads();
        uint32_t base = sb + (st % 3)*TR_STAGE;
        #pragma unroll
        for (int kc = 0; kc < 2; kc++) {
            uint32_t kb = coff + kc*32;
            uint32_t Ah[2][4];
            #pragma unroll
            for (int mt=0; mt<2; mt++)
                ldm_x4(Ah[mt], base + (uint32_t)((m0 + mt*16 + l16) * TSROW) + kb);
            #pragma unroll
            for (int np=0; np<4; np++) {
                uint32_t Bh[4];
                ldm_x4(Bh, base + TPLANE + (uint32_t)((n0 + np*16 + l16) * TSROW) + kb);
                #pragma unroll
                for (int h=0; h<2; h++) {
                    uint32_t bh[2] = {Bh[h], Bh[2+h]};
                    int nt = np*2 + h;
                    #pragma unroll
                    for (int mt=0; mt<2; mt++)
                        mma_f16(acc[mt][nt], Ah[mt], bh);
                }
            }
        }
        __syncthreads();
        if (st + 3 < 16) load_stage(st + 3, st % 3);
    }

    uint32_t* O = Ot + (size_t)cz*(NN_/2);
    #pragma unroll
    for (int mt=0; mt<2; mt++) {
        int r = i0 + m0 + mt*16 + g;
        #pragma unroll
        for (int nt=0; nt<8; nt++) {
            int cl = j0 + n0 + nt*8 + 2*tg;
            O[(size_t)r*(N_/2) + cl/2]     = pack_h2(acc[mt][nt][0], acc[mt][nt][1]);
            O[(size_t)(r+8)*(N_/2) + cl/2] = pack_h2(acc[mt][nt][2], acc[mt][nt][3]);
        }
    }
}

// ---------------------------------------------------------------------------
// out_fused: 64-ij tile, 256 thr, 3 CTAs/SM.
// NEW: XOR-swizzled OT staging (kills LN transpose bank conflicts) and
// 1-term X GEMM (hi plane only).
// smem: OT-staging/ON [0,34816) | WO [34816,69632) | ws 1KB
// ---------------------------------------------------------------------------
#define OF_WO   34816
#define OF_WS   69632
#define OF_SMEM 70656

__global__ __launch_bounds__(256, 3) void out_fused(
    const uint32_t* __restrict__ ot, const uint32_t* __restrict__ gate,
    const float* __restrict__ lnw, const float* __restrict__ lnb,
    const uint32_t* __restrict__ WoH,
    float* __restrict__ out)
{
    extern __shared__ char sm[];
    uint32_t sb = smem_u32(sm);
    int t = threadIdx.x, warp = t>>5, lane = t&31, g = lane>>2, tg = lane&3;
    int l16 = lane & 15;
    uint32_t coff = (uint32_t)((lane >> 4) * 16);
    int m0 = (warp & 1) * 32, n0 = (warp >> 1) * 32;
    size_t ij0 = (size_t)blockIdx.x * 64;

    // group1: OT16 tile: 128 c-rows x 8 chunks of 16B, chunk-swizzled by c
    #pragma unroll
    for (int i = 0; i < 4; i++) {
        int e = i*256 + t, c = e >> 3, ch = e & 7;
        int chs = ch ^ (c & 7);
        cp16s(sb + (uint32_t)(c*XROW + chs*16),
              (const char*)(ot + (size_t)c*(NN_/2) + ij0/2) + ch*16);
    }
    cp_commit();
    // group2: WO hi plane (128 rows)
    #pragma unroll
    for (int i = 0; i < 8; i++) {
        int e = i*256 + t;
        int r = e >> 4, ch = e & 15;
        cp16s(sb + OF_WO + (uint32_t)(r*XROW + ch*16), WoH + (size_t)r*64 + ch*4);
    }
    cp_commit();

    if (t < 128) {
        ((float*)(sm + OF_WS))[t]       = lnw[t];
        ((float*)(sm + OF_WS))[128 + t] = lnb[t];
    }

    CP_WAIT(1); __syncthreads();   // OT16 ready

    // LN over c per ij -> ON hi plane (in place over staging region)
    {
        float* wv = (float*)(sm + OF_WS);
        int ij = t >> 2, q = t & 3;
        int chunk = ij >> 3, sub = (ij & 7) * 2;
        float y[32];
        float s1 = 0.f, s2 = 0.f;
        #pragma unroll
        for (int i = 0; i < 32; i++) {
            int c = q*32 + i;
            int chs = chunk ^ (c & 7);
            __half h = *(const __half*)(sm + c*XROW + chs*16 + sub);
            float v = __half2float(h);
            y[i] = v; s1 += v; s2 += v*v;
        }
        s1 += __shfl_xor_sync(~0u, s1, 1); s2 += __shfl_xor_sync(~0u, s2, 1);
        s1 += __shfl_xor_sync(~0u, s1, 2); s2 += __shfl_xor_sync(~0u, s2, 2);
        float mu  = s1 * (1.f/128.f);
        float var = s2 * (1.f/128.f) - mu*mu;
        float inv = rsqrtf(var + 1e-5f);
        __syncthreads();                    // all reads done before overwrite
        uint32_t* oh = (uint32_t*)(sm + ij*XROW);
        #pragma unroll
        for (int j = 0; j < 16; j++) {
            int c0 = q*32 + 2*j;
            float y0 = (y[2*j]   - mu) * inv * wv[c0]   + wv[128 + c0];
            float y1 = (y[2*j+1] - mu) * inv * wv[c0+1] + wv[128 + c0 + 1];
            oh[q*16 + j] = pack_h2(y0, y1);
        }
    }
    CP_WAIT(0); __syncthreads();   // ON written + WO ready

    float acc[2][4][4];
    #pragma unroll
    for (int mt=0; mt<2; mt++)
        #pragma unroll
        for (int nt=0; nt<4; nt++)
            #pragma unroll
            for (int q=0; q<4; q++) acc[mt][nt][q]=0.f;

    gemm64(sb, sb + OF_WO, acc, m0, n0, l16, coff);

    #pragma unroll
    for (int mt=0; mt<2; mt++) {
        size_t rl = ij0 + m0 + mt*16 + g;
        size_t rh = rl + 8;
        #pragma unroll
        for (int nt=0; nt<4; nt++) {
            int cl = n0 + nt*8 + 2*tg;
            __half2 glh = *(const __half2*)(gate + rl*64 + cl/2);
            __half2 ghh = *(const __half2*)(gate + rh*64 + cl/2);
            float2 gl = __half22float2(glh);
            float2 gh = __half22float2(ghh);
            *(float2*)(out + rl*C_ + cl) =
                make_float2(gl.x * acc[mt][nt][0], gl.y * acc[mt][nt][1]);
            *(float2*)(out + rh*C_ + cl) =
                make_float2(gh.x * acc[mt][nt][2], gh.y * acc[mt][nt][3]);
        }
    }
}

// ---------------------------------------------------------------------------
extern "C" void kernel_launch(void* const* d_in, const int* in_sizes, int n_in,
                              void* d_out, int out_size)
{
    const float* z      = (const float*)d_in[0];
    const float* mask   = (const float*)d_in[1];
    const float* ln_i_w = (const float*)d_in[2];
    const float* ln_i_b = (const float*)d_in[3];
    const float* ln_o_w = (const float*)d_in[4];
    const float* ln_o_b = (const float*)d_in[5];
    const float* w_pa   = (const float*)d_in[6];
    const float* w_pb   = (const float*)d_in[7];
    const float* w_ga   = (const float*)d_in[8];
    const float* w_gb   = (const float*)d_in[9];
    const float* w_g    = (const float*)d_in[10];
    const float* w_o    = (const float*)d_in[11];
    float* out = (float*)d_out;

    uint32_t *ath, *bth, *wh, *gt, *ot;
    cudaGetSymbolAddress((void**)&ath, g_ath);
    cudaGetSymbolAddress((void**)&bth, g_bth);
    cudaGetSymbolAddress((void**)&wh,  g_wh);
    cudaGetSymbolAddress((void**)&gt,  g_gt);
    cudaGetSymbolAddress((void**)&ot,  g_ot);

    cudaFuncSetAttribute(proj_fused, cudaFuncAttributeMaxDynamicSharedMemorySize, PJ_SMEM);
    cudaFuncSetAttribute(out_fused,  cudaFuncAttributeMaxDynamicSharedMemorySize, OF_SMEM);
    cudaFuncSetAttribute(tri_lm,     cudaFuncAttributeMaxDynamicSharedMemorySize, TR_SMEM);

    // weight plane order: ga=0, pa=1, gb=2, pb=3, g=4, o=5
    split_w_lm<<<dim3(32, 6), 256>>>(w_ga, w_pa, w_gb, w_pb, w_g, w_o, wh);
    // LN(z) + 5 projections fused (1-term fp16, 64-row tiles, 2 CTAs/SM)
    proj_fused<<<NN_/64, 256, PJ_SMEM>>>(z, mask, ln_i_w, ln_i_b, wh,
                                         ath, bth, gt);
    // triangle einsum (1-term fp16) -> ot fp16 c-major
    tri_lm<<<dim3(N_/128, N_/128, C_), 256, TR_SMEM>>>(ath, bth, ot);
    // transpose+LN+GEMM+gate fused (1-term, swizzled staging, 3 CTAs/SM)
    out_fused<<<NN_/64, 256, OF_SMEM>>>(ot, gt, ln_o_w, ln_o_b,
                                        wh + 5*C_*64, out);
}